// round 1
// baseline (speedup 1.0000x reference)
#include <cuda_runtime.h>
#include <cstdint>

#define THREADS 128
// smem layout (floats): slab[32*3*66]=6336 | wbuf[128*36]=4608 | Hsm[128*68]=8704
#define SLAB_F   6336
#define WBUF_F   4608
#define HSM_F    8704
#define SMEM_BYTES ((SLAB_F + WBUF_F + HSM_F) * 4)

__device__ __forceinline__ unsigned long long bcast2(float v) {
    unsigned long long r;
    asm("mov.b64 %0, {%1, %1};" : "=l"(r) : "f"(v));
    return r;
}
__device__ __forceinline__ void unpack2(unsigned long long v, float& lo, float& hi) {
    asm("mov.b64 {%0, %1}, %2;" : "=f"(lo), "=f"(hi) : "l"(v));
}
__device__ __forceinline__ unsigned long long fma2(unsigned long long a,
                                                   unsigned long long b,
                                                   unsigned long long c) {
    unsigned long long d;
    asm("fma.rn.f32x2 %0, %1, %2, %3;" : "=l"(d) : "l"(a), "l"(b), "l"(c));
    return d;
}

__global__ __launch_bounds__(THREADS)
void lp_kernel(const float* __restrict__ z, const float* __restrict__ W1,
               const float* __restrict__ b1, const float* __restrict__ W2,
               const float* __restrict__ b2, float* __restrict__ out)
{
    extern __shared__ float smem[];
    float* slab = smem;                      // [k][r][c] = [32][3][66]
    float* wbuf = smem + SLAB_F;             // GEMM1: [32][132] ; GEMM2: [128][36]
    float* Hsm  = smem + SLAB_F + WBUF_F;    // [d][m] = [128][68]

    const int x0  = blockIdx.x * 64;
    const int y   = blockIdx.y;
    const int b   = blockIdx.z;
    const int tid = threadIdx.x;
    const int tm  = tid & 15;      // 16 m-groups of 4 pixels
    const int tn  = tid >> 4;      // 8 n-groups of 16 hidden
    const int tm4  = tm * 4;
    const int tn16 = tn * 16;

    const float* zb = z + ((size_t)b * 32) * 65536;

    // ---- stage z slab: rows y-1..y+1, cols x0-1..x0+64, zero-padded ----
    for (int idx = tid; idx < SLAB_F; idx += THREADS) {
        int k   = idx / 198;
        int rem = idx - k * 198;
        int r   = rem / 66;
        int c   = rem - r * 66;
        int yy = y - 1 + r;
        int xx = x0 - 1 + c;
        float v = 0.0f;
        if ((unsigned)yy < 256u && (unsigned)xx < 256u)
            v = zb[(size_t)k * 65536 + yy * 256 + xx];
        slab[idx] = v;
    }

    // ---- GEMM1: h[64 px][128 hid], K = 32 ch * 8 taps (center skipped) ----
    unsigned long long acc[4][8];
    #pragma unroll
    for (int i = 0; i < 4; ++i)
        #pragma unroll
        for (int j = 0; j < 8; ++j) acc[i][j] = 0ULL;

    for (int ch = 0; ch < 8; ++ch) {        // 8 chunks of 4 channels
        __syncthreads();
        // stage W1 chunk transposed: wbuf[tt*132 + d] = W1[d*288 + k*9 + p]
        #pragma unroll
        for (int it = 0; it < 32; ++it) {
            int idx = it * THREADS + tid;   // 4096 elems, t-fastest for coalescing
            int d  = idx >> 5;
            int tt = idx & 31;
            int q  = tt & 7;
            int kk = tt >> 3;
            int p  = q + (q >= 4);          // skip center tap (p==4)
            wbuf[tt * 132 + d] = W1[d * 288 + (ch * 4 + kk) * 9 + p];
        }
        __syncthreads();

        #pragma unroll
        for (int kk = 0; kk < 4; ++kk) {
            const float* sk = slab + (ch * 4 + kk) * 198 + tm4;
            #pragma unroll
            for (int q = 0; q < 8; ++q) {
                const int p  = q + (q >= 4);
                const int di = p / 3, dj = p % 3;
                const float* ar = sk + di * 66 + dj;
                unsigned long long A[4];
                A[0] = bcast2(ar[0]);
                A[1] = bcast2(ar[1]);
                A[2] = bcast2(ar[2]);
                A[3] = bcast2(ar[3]);
                const ulonglong2* wr =
                    (const ulonglong2*)(wbuf + (kk * 8 + q) * 132 + tn16);
                unsigned long long Wp[8];
                {
                    ulonglong2 t0 = wr[0]; Wp[0] = t0.x; Wp[1] = t0.y;
                    ulonglong2 t1 = wr[1]; Wp[2] = t1.x; Wp[3] = t1.y;
                    ulonglong2 t2 = wr[2]; Wp[4] = t2.x; Wp[5] = t2.y;
                    ulonglong2 t3 = wr[3]; Wp[6] = t3.x; Wp[7] = t3.y;
                }
                #pragma unroll
                for (int i = 0; i < 4; ++i)
                    #pragma unroll
                    for (int j = 0; j < 8; ++j)
                        acc[i][j] = fma2(A[i], Wp[j], acc[i][j]);
            }
        }
    }

    // ---- bias + ReLU, write H transposed [d][m] ----
    float bias1[16];
    #pragma unroll
    for (int j = 0; j < 16; ++j) bias1[j] = __ldg(&b1[tn16 + j]);

    #pragma unroll
    for (int i = 0; i < 4; ++i) {
        #pragma unroll
        for (int j = 0; j < 8; ++j) {
            float h0, h1;
            unpack2(acc[i][j], h0, h1);
            h0 = fmaxf(h0 + bias1[2 * j], 0.0f);
            h1 = fmaxf(h1 + bias1[2 * j + 1], 0.0f);
            int d0 = tn16 + 2 * j;
            Hsm[d0 * 68 + tm4 + i]       = h0;
            Hsm[(d0 + 1) * 68 + tm4 + i] = h1;
        }
    }
    __syncthreads();  // H ready; wbuf free for W2

    // stage W2 transposed: wbuf[t*36 + n] = W2[n*128 + t]
    #pragma unroll
    for (int it = 0; it < 32; ++it) {
        int idx = it * THREADS + tid;       // 4096 elems, t-fastest
        int n = idx >> 7;
        int t = idx & 127;
        wbuf[t * 36 + n] = W2[n * 128 + t];
    }
    __syncthreads();

    // ---- GEMM2: logits[64 px][32], K = 128 ----
    unsigned long long acc2[4][2];
    #pragma unroll
    for (int i = 0; i < 4; ++i) { acc2[i][0] = 0ULL; acc2[i][1] = 0ULL; }

    const int tn4 = tn * 4;
    #pragma unroll 8
    for (int t = 0; t < 128; ++t) {
        const float4 av = *(const float4*)(Hsm + t * 68 + tm4);
        const ulonglong2 bv = *(const ulonglong2*)(wbuf + t * 36 + tn4);
        unsigned long long A[4];
        A[0] = bcast2(av.x); A[1] = bcast2(av.y);
        A[2] = bcast2(av.z); A[3] = bcast2(av.w);
        #pragma unroll
        for (int i = 0; i < 4; ++i) {
            acc2[i][0] = fma2(A[i], bv.x, acc2[i][0]);
            acc2[i][1] = fma2(A[i], bv.y, acc2[i][1]);
        }
    }

    // ---- bias + vectorized store ----
    float bz[4];
    #pragma unroll
    for (int c = 0; c < 4; ++c) bz[c] = __ldg(&b2[tn4 + c]);

    float r[4][4];  // [n][m]
    #pragma unroll
    for (int i = 0; i < 4; ++i) {
        float lo, hi;
        unpack2(acc2[i][0], lo, hi);
        r[0][i] = lo + bz[0];
        r[1][i] = hi + bz[1];
        unpack2(acc2[i][1], lo, hi);
        r[2][i] = lo + bz[2];
        r[3][i] = hi + bz[3];
    }
    #pragma unroll
    for (int n = 0; n < 4; ++n) {
        int nn = tn4 + n;
        float4 v = make_float4(r[n][0], r[n][1], r[n][2], r[n][3]);
        *(float4*)(out + (((size_t)b * 32 + nn) * 256 + y) * 256 + x0 + tm4) = v;
    }
}

extern "C" void kernel_launch(void* const* d_in, const int* in_sizes, int n_in,
                              void* d_out, int out_size) {
    const float* z  = (const float*)d_in[0];
    const float* W1 = (const float*)d_in[1];
    const float* b1 = (const float*)d_in[2];
    const float* W2 = (const float*)d_in[3];
    const float* b2 = (const float*)d_in[4];
    float* out = (float*)d_out;

    cudaFuncSetAttribute(lp_kernel, cudaFuncAttributeMaxDynamicSharedMemorySize,
                         SMEM_BYTES);
    dim3 grid(4, 256, 8);   // x-tiles, rows, batch
    dim3 block(THREADS);
    lp_kernel<<<grid, block, SMEM_BYTES>>>(z, W1, b1, W2, b2, out);
}